// round 1
// baseline (speedup 1.0000x reference)
#include <cuda_runtime.h>
#include <math.h>

// Problem shape (fixed by the dataset)
#define BATCH 4
#define SEQ   8192
#define DIM   512

// Kernel 1 (outer-product GEMM): tiles 128x128, K-split 2
#define TM    128
#define TN    128
#define TK    16
#define SPLITS 2
#define KSPLIT (SEQ/SPLITS)
#define NITER (KSPLIT/TK)
#define SROW  136          // smem row stride (words) for [k][x] tiles: (8k+x)%32 conflict-free
#define TPB   256

// Kernel 2 (C = W @ M + bias*v): K=512
#define TK2   16
#define NIT2  (DIM/TK2)
#define AR2   20           // smem row stride for [m][k] W tile: (20m+k)%32 conflict-free

// Scratch: partial M (per split) and partial v
__device__ float g_P[(size_t)SPLITS*BATCH*DIM*DIM];   // 8 MB
__device__ float g_V[SPLITS*BATCH*DIM];

__device__ __forceinline__ unsigned tf32_rna(float x){
    unsigned u; asm("cvt.rna.tf32.f32 %0, %1;" : "=r"(u) : "f"(x)); return u;
}

__device__ __forceinline__ void mma_tf32(float c[4], const unsigned a[4], unsigned b0, unsigned b1){
    asm("mma.sync.aligned.m16n8k8.row.col.f32.tf32.tf32.f32 "
        "{%0,%1,%2,%3},{%4,%5,%6,%7},{%8,%9},{%0,%1,%2,%3};"
        : "+f"(c[0]), "+f"(c[1]), "+f"(c[2]), "+f"(c[3])
        : "r"(a[0]), "r"(a[1]), "r"(a[2]), "r"(a[3]), "r"(b0), "r"(b1));
}

// ---------------------------------------------------------------------------
// Kernel 1: M[b,d',d] = sum_t w_t * H[b,t,d'] * E[b,t,d]   (per K-split partials)
//           v[b,d]    = sum_t w_t * E[b,t,d]               (mt==0 CTAs only)
// Natural global layout is [t][feature] == [k][m]/[k][n]: no transpose needed.
// ---------------------------------------------------------------------------
__global__ void __launch_bounds__(TPB,1)
k1_outer(const float* __restrict__ H, const float* __restrict__ E)
{
    __shared__ __align__(16) unsigned As[2][TK][SROW];
    __shared__ __align__(16) unsigned Bs[2][TK][SROW];
    __shared__ float vsm[TPB*4];

    const int tid  = threadIdx.x;
    const int lane = tid & 31;
    const int warp = tid >> 5;
    const int wm = warp & 3, wn = warp >> 2;   // 4x2 warp grid -> warp tile 32x64
    const int tg = lane & 3;                   // threadID_in_group
    const int gp = lane >> 2;                  // groupID

    const int x     = blockIdx.x;
    const int split = x & (SPLITS-1);
    const int nt    = (x >> 1) & 3;
    const int mt    = (x >> 3) & 3;
    const int b     = x >> 5;

    const int k0 = split * KSPLIT;
    const float* Ag = H + ((size_t)b*SEQ + k0)*DIM + mt*TM;
    const float* Bg = E + ((size_t)b*SEQ + k0)*DIM + nt*TN;

    const int kr = tid >> 5;   // 0..7 (row within half K-chunk)
    const int c4 = tid & 31;   // float4 column
    const float* Ap = Ag + (size_t)kr*DIM + 4*c4;
    const float* Bp = Bg + (size_t)kr*DIM + 4*c4;

    // Replicate reference: alpha = float32(exp(-pi/S)); ln(alpha) in fp32
    const float lnalpha = logf((float)0.9996165783279395);
    const float mult8   = expf(-8.0f * lnalpha);  // w(t+8) = w(t)*alpha^-8... (exponent drops by 8)

    float acc[2][8][4];
    #pragma unroll
    for (int i=0;i<2;i++){ 
        #pragma unroll
        for (int j=0;j<8;j++){ 
            #pragma unroll
            for (int r=0;r<4;r++) acc[i][j][r]=0.f; } }

    float va0=0.f, va1=0.f, va2=0.f, va3=0.f;

    float4 ra0, ra1, rb0, rb1;

    auto store_tile = [&](int bf, int it){
        const int t0 = k0 + it*TK + kr;
        float w0 = expf((float)(SEQ-1 - t0) * lnalpha);
        float w1 = w0 * mult8;                 // weight for row kr+8
        uint4 u;
        u.x = tf32_rna(ra0.x); u.y = tf32_rna(ra0.y); u.z = tf32_rna(ra0.z); u.w = tf32_rna(ra0.w);
        *(uint4*)&As[bf][kr][4*c4] = u;
        u.x = tf32_rna(ra1.x); u.y = tf32_rna(ra1.y); u.z = tf32_rna(ra1.z); u.w = tf32_rna(ra1.w);
        *(uint4*)&As[bf][kr+8][4*c4] = u;
        float s0x = rb0.x*w0, s0y = rb0.y*w0, s0z = rb0.z*w0, s0w = rb0.w*w0;
        float s1x = rb1.x*w1, s1y = rb1.y*w1, s1z = rb1.z*w1, s1w = rb1.w*w1;
        va0 += s0x + s1x; va1 += s0y + s1y; va2 += s0z + s1z; va3 += s0w + s1w;
        u.x = tf32_rna(s0x); u.y = tf32_rna(s0y); u.z = tf32_rna(s0z); u.w = tf32_rna(s0w);
        *(uint4*)&Bs[bf][kr][4*c4] = u;
        u.x = tf32_rna(s1x); u.y = tf32_rna(s1y); u.z = tf32_rna(s1z); u.w = tf32_rna(s1w);
        *(uint4*)&Bs[bf][kr+8][4*c4] = u;
    };

    auto do_mma = [&](int bf, int kk){
        unsigned a[2][4];
        #pragma unroll
        for (int i=0;i<2;i++){
            const int mb = 32*wm + 16*i + gp;
            a[i][0] = As[bf][kk+tg  ][mb  ];
            a[i][1] = As[bf][kk+tg  ][mb+8];
            a[i][2] = As[bf][kk+tg+4][mb  ];
            a[i][3] = As[bf][kk+tg+4][mb+8];
        }
        #pragma unroll
        for (int j=0;j<8;j++){
            const int nb = 64*wn + 8*j + gp;
            unsigned b0 = Bs[bf][kk+tg  ][nb];
            unsigned b1 = Bs[bf][kk+tg+4][nb];
            mma_tf32(acc[0][j], a[0], b0, b1);
            mma_tf32(acc[1][j], a[1], b0, b1);
        }
    };

    // prologue
    ra0 = *(const float4*)(Ap);
    ra1 = *(const float4*)(Ap + 8*DIM);
    rb0 = *(const float4*)(Bp);
    rb1 = *(const float4*)(Bp + 8*DIM);
    store_tile(0, 0);
    __syncthreads();

    int buf = 0;
    const size_t step = (size_t)TK*DIM;
    for (int it = 0; it < NITER; ++it){
        if (it + 1 < NITER){
            const float* Apn = Ap + (size_t)(it+1)*step;
            const float* Bpn = Bp + (size_t)(it+1)*step;
            ra0 = *(const float4*)(Apn);
            ra1 = *(const float4*)(Apn + 8*DIM);
            rb0 = *(const float4*)(Bpn);
            rb1 = *(const float4*)(Bpn + 8*DIM);
        }
        do_mma(buf, 0);
        do_mma(buf, 8);
        if (it + 1 < NITER) store_tile(buf^1, it+1);
        __syncthreads();
        buf ^= 1;
    }

    // write partial M tile (plain stores, no atomics)
    float* Pp = g_P + (((size_t)(split*BATCH + b))*DIM + mt*TM)*DIM + nt*TN;
    #pragma unroll
    for (int i=0;i<2;i++){
        const int r = 32*wm + 16*i + gp;
        #pragma unroll
        for (int j=0;j<8;j++){
            const int cc = 64*wn + 8*j + 2*tg;
            *(float2*)&Pp[(size_t)r*DIM + cc]     = make_float2(acc[i][j][0], acc[i][j][1]);
            *(float2*)&Pp[(size_t)(r+8)*DIM + cc] = make_float2(acc[i][j][2], acc[i][j][3]);
        }
    }

    // partial v (only one m-tile per (split,b,nt) contributes; unique writers -> plain stores)
    if (mt == 0){
        vsm[tid*4+0]=va0; vsm[tid*4+1]=va1; vsm[tid*4+2]=va2; vsm[tid*4+3]=va3;
        __syncthreads();
        if (tid < 32){
            float s0=0.f,s1=0.f,s2=0.f,s3=0.f;
            #pragma unroll
            for (int j=0;j<8;j++){
                const int t2 = (tid + 32*j)*4;
                s0+=vsm[t2]; s1+=vsm[t2+1]; s2+=vsm[t2+2]; s3+=vsm[t2+3];
            }
            float* vp = g_V + ((size_t)split*BATCH + b)*DIM + nt*TN + tid*4;
            vp[0]=s0; vp[1]=s1; vp[2]=s2; vp[3]=s3;
        }
    }
}

// ---------------------------------------------------------------------------
// Kernel 2: C[b,s,d] = sum_d' W[s,d'] * M[b,d',d] + bias[s]*v[b,d]
// M is consumed as the sum of the K-split partials during the B-tile load.
// ---------------------------------------------------------------------------
__global__ void __launch_bounds__(TPB,1)
k2_proj(const float* __restrict__ Wm, const float* __restrict__ bias, float* __restrict__ out)
{
    __shared__ __align__(16) unsigned As2[2][TM][AR2];
    __shared__ __align__(16) unsigned Bs2[2][TK2][SROW];

    const int tid  = threadIdx.x;
    const int lane = tid & 31;
    const int warp = tid >> 5;
    const int wm = warp & 3, wn = warp >> 2;
    const int tg = lane & 3;
    const int gp = lane >> 2;

    const int x  = blockIdx.x;
    const int nt = x & 3;
    const int mt = (x >> 2) & 3;
    const int b  = x >> 4;

    // A-load coords (W tile 128 x 16): 2 float4 per thread
    const int am = tid >> 2;          // 0..63 (and +64)
    const int ak4 = tid & 3;
    // B-load coords (M tile 16 x 128): 2 float4 per thread
    const int bk = tid >> 5;          // 0..7 (and +8)
    const int bn4 = tid & 31;

    const float* Wg = Wm + (size_t)(mt*TM)*DIM;

    float acc[2][8][4];
    #pragma unroll
    for (int i=0;i<2;i++){ 
        #pragma unroll
        for (int j=0;j<8;j++){ 
            #pragma unroll
            for (int r=0;r<4;r++) acc[i][j][r]=0.f; } }

    float4 wa0, wa1, mb0, mb1;

    auto load_tile = [&](int it){
        const float* p0 = Wg + (size_t)am*DIM + it*TK2 + 4*ak4;
        wa0 = *(const float4*)(p0);
        wa1 = *(const float4*)(p0 + (size_t)64*DIM);
        mb0 = make_float4(0.f,0.f,0.f,0.f);
        mb1 = make_float4(0.f,0.f,0.f,0.f);
        #pragma unroll
        for (int p=0;p<SPLITS;p++){
            const float* q = g_P + (((size_t)(p*BATCH + b))*DIM + it*TK2 + bk)*DIM + nt*TN + 4*bn4;
            float4 v0 = *(const float4*)(q);
            float4 v1 = *(const float4*)(q + (size_t)8*DIM);
            mb0.x+=v0.x; mb0.y+=v0.y; mb0.z+=v0.z; mb0.w+=v0.w;
            mb1.x+=v1.x; mb1.y+=v1.y; mb1.z+=v1.z; mb1.w+=v1.w;
        }
    };

    auto store_tile = [&](int bf){
        uint4 u;
        u.x=tf32_rna(wa0.x); u.y=tf32_rna(wa0.y); u.z=tf32_rna(wa0.z); u.w=tf32_rna(wa0.w);
        *(uint4*)&As2[bf][am][4*ak4] = u;
        u.x=tf32_rna(wa1.x); u.y=tf32_rna(wa1.y); u.z=tf32_rna(wa1.z); u.w=tf32_rna(wa1.w);
        *(uint4*)&As2[bf][am+64][4*ak4] = u;
        u.x=tf32_rna(mb0.x); u.y=tf32_rna(mb0.y); u.z=tf32_rna(mb0.z); u.w=tf32_rna(mb0.w);
        *(uint4*)&Bs2[bf][bk][4*bn4] = u;
        u.x=tf32_rna(mb1.x); u.y=tf32_rna(mb1.y); u.z=tf32_rna(mb1.z); u.w=tf32_rna(mb1.w);
        *(uint4*)&Bs2[bf][bk+8][4*bn4] = u;
    };

    auto do_mma = [&](int bf, int kk){
        unsigned a[2][4];
        #pragma unroll
        for (int i=0;i<2;i++){
            const int mb = 32*wm + 16*i + gp;
            a[i][0] = As2[bf][mb  ][kk+tg  ];
            a[i][1] = As2[bf][mb+8][kk+tg  ];
            a[i][2] = As2[bf][mb  ][kk+tg+4];
            a[i][3] = As2[bf][mb+8][kk+tg+4];
        }
        #pragma unroll
        for (int j=0;j<8;j++){
            const int nb = 64*wn + 8*j + gp;
            unsigned b0 = Bs2[bf][kk+tg  ][nb];
            unsigned b1 = Bs2[bf][kk+tg+4][nb];
            mma_tf32(acc[0][j], a[0], b0, b1);
            mma_tf32(acc[1][j], a[1], b0, b1);
        }
    };

    load_tile(0);
    store_tile(0);
    __syncthreads();

    int buf = 0;
    for (int it = 0; it < NIT2; ++it){
        if (it + 1 < NIT2) load_tile(it+1);
        do_mma(buf, 0);
        do_mma(buf, 8);
        if (it + 1 < NIT2) store_tile(buf^1);
        __syncthreads();
        buf ^= 1;
    }

    // epilogue: + bias[s] * v[d]
    float* Co = out + (((size_t)b)*DIM + mt*TM)*DIM + nt*TN;
    float bi[2][2];
    #pragma unroll
    for (int i=0;i<2;i++){
        const int r = 32*wm + 16*i + gp;
        bi[i][0] = bias[mt*TM + r];
        bi[i][1] = bias[mt*TM + r + 8];
    }
    #pragma unroll
    for (int j=0;j<8;j++){
        const int cc = 64*wn + 8*j + 2*tg;
        const int cg = nt*TN + cc;
        float v0 = 0.f, v1 = 0.f;
        #pragma unroll
        for (int p=0;p<SPLITS;p++){
            const float* vp = g_V + ((size_t)p*BATCH + b)*DIM + cg;
            v0 += vp[0]; v1 += vp[1];
        }
        #pragma unroll
        for (int i=0;i<2;i++){
            const int r = 32*wm + 16*i + gp;
            *(float2*)&Co[(size_t)r*DIM + cc] =
                make_float2(acc[i][j][0] + bi[i][0]*v0, acc[i][j][1] + bi[i][0]*v1);
            *(float2*)&Co[(size_t)(r+8)*DIM + cc] =
                make_float2(acc[i][j][2] + bi[i][1]*v0, acc[i][j][3] + bi[i][1]*v1);
        }
    }
}

extern "C" void kernel_launch(void* const* d_in, const int* in_sizes, int n_in,
                              void* d_out, int out_size)
{
    const float* H    = (const float*)d_in[0];   // hidden_states (4,8192,512)
    const float* E    = (const float*)d_in[1];   // positional_encodings (4,8192,512)
    const float* Wm   = (const float*)d_in[2];   // W (512,512)
    const float* bias = (const float*)d_in[3];   // b (512,)
    float* out = (float*)d_out;                  // (4,512,512)

    k1_outer<<<BATCH*4*4*SPLITS, TPB>>>(H, E);
    k2_proj<<<BATCH*4*4, TPB>>>(Wm, bias, out);
}

// round 2
// speedup vs baseline: 1.5091x; 1.5091x over previous
#include <cuda_runtime.h>
#include <math.h>

// Problem shape (fixed by the dataset)
#define BATCH 4
#define SEQ   8192
#define DIM   512

// Kernel 1 (outer-product GEMM): tiles 128x128, K-split 2, 4-stage cp.async
#define TM    128
#define TN    128
#define TK    16
#define SPLITS 2
#define KSPLIT (SEQ/SPLITS)
#define NITER (KSPLIT/TK)
#define SROW  136          // smem row stride (words): conflict-free frag reads
#define TPB   256
#define K1_STAGES 4
#define K1_OP_W   (TK*SROW)            // words per operand tile
#define K1_STG_W  (2*K1_OP_W)          // words per stage (A+B)
#define K1_SMEM_B (K1_STAGES*K1_STG_W*4)

// Kernel 2 (C = W @ M + bias*v): K=512, 3-stage cp.async
#define TK2   16
#define NIT2  (DIM/TK2)
#define AR2   20           // smem row stride (words) for [m][k] W tile
#define K2_STAGES 3
#define K2_A_W   (TM*AR2)              // 2560 words
#define K2_B_W   (TK2*SROW)            // per-partial B tile words
#define K2_STG_W (K2_A_W + 2*K2_B_W)   // 2560 + 4352 = 6912
#define K2_SMEM_B (K2_STAGES*K2_STG_W*4)

// Scratch: partial M (per split) and partial v
__device__ float g_P[(size_t)SPLITS*BATCH*DIM*DIM];   // 8 MB
__device__ float g_V[SPLITS*BATCH*DIM];

__device__ __forceinline__ unsigned tf32_rna(float x){
    unsigned u; asm("cvt.rna.tf32.f32 %0, %1;" : "=r"(u) : "f"(x)); return u;
}
__device__ __forceinline__ void mma_tf32(float c[4], const unsigned a[4], unsigned b0, unsigned b1){
    asm("mma.sync.aligned.m16n8k8.row.col.f32.tf32.tf32.f32 "
        "{%0,%1,%2,%3},{%4,%5,%6,%7},{%8,%9},{%0,%1,%2,%3};"
        : "+f"(c[0]), "+f"(c[1]), "+f"(c[2]), "+f"(c[3])
        : "r"(a[0]), "r"(a[1]), "r"(a[2]), "r"(a[3]), "r"(b0), "r"(b1));
}
__device__ __forceinline__ void cp16(unsigned dst, const float* src){
    asm volatile("cp.async.cg.shared.global [%0], [%1], 16;\n" :: "r"(dst), "l"(src));
}
#define CP_COMMIT() asm volatile("cp.async.commit_group;\n" ::: "memory")
#define CP_WAIT(n)  asm volatile("cp.async.wait_group %0;\n" :: "n"(n) : "memory")

// ---------------------------------------------------------------------------
// Kernel 1: M[b,d',d] = sum_t w_t * H[b,t,d'] * E[b,t,d]   (per K-split partials)
//           v[b,d]    = sum_t w_t * E[b,t,d]               (mt==0 CTAs, wm==0 warps)
// Decay weight w_t is applied to the A-side (H) fragments; v is accumulated
// from the raw B-side (E) fragments with the same weights.
// ---------------------------------------------------------------------------
__global__ void __launch_bounds__(TPB,1)
k1_outer(const float* __restrict__ H, const float* __restrict__ E)
{
    extern __shared__ float sm1[];

    const int tid  = threadIdx.x;
    const int lane = tid & 31;
    const int warp = tid >> 5;
    const int wm = warp & 3, wn = warp >> 2;   // 4x2 warp grid -> warp tile 32x64
    const int tg = lane & 3;
    const int gp = lane >> 2;

    const int x     = blockIdx.x;
    const int split = x & (SPLITS-1);
    const int nt    = (x >> 1) & 3;
    const int mt    = (x >> 3) & 3;
    const int b     = x >> 5;

    const int k0 = split * KSPLIT;
    const float* Ag = H + ((size_t)b*SEQ + k0)*DIM + mt*TM;
    const float* Bg = E + ((size_t)b*SEQ + k0)*DIM + nt*TN;

    // cp.async coordinates: thread handles rows kr and kr+8, one float4 column
    const int kr = tid >> 5;   // 0..7
    const int c4 = tid & 31;   // float4 column (0..31)
    const float* Ap = Ag + (size_t)kr*DIM + 4*c4;
    const float* Bp = Bg + (size_t)kr*DIM + 4*c4;
    const size_t step = (size_t)TK*DIM;

    const unsigned sm_base = (unsigned)__cvta_generic_to_shared(sm1);
    const unsigned dA0 = sm_base + 4u*(kr*SROW + 4*c4);
    const unsigned dB0 = sm_base + 4u*(K1_OP_W + kr*SROW + 4*c4);

    auto issue_stage = [&](int it){
        const unsigned so = (unsigned)((it & (K1_STAGES-1)) * K1_STG_W * 4);
        const float* a = Ap + (size_t)it*step;
        const float* bb = Bp + (size_t)it*step;
        cp16(dA0 + so, a);
        cp16(dA0 + so + 4u*8*SROW, a + 8*DIM);
        cp16(dB0 + so, bb);
        cp16(dB0 + so + 4u*8*SROW, bb + 8*DIM);
    };

    // decay weights
    const float lnalpha = logf((float)0.9996165783279395);
    const float c4f  = expf(-4.0f*lnalpha);
    const float c8f  = expf(-8.0f*lnalpha);
    const float c12f = expf(-12.0f*lnalpha);
    const float c16f = expf(-16.0f*lnalpha);
    float wt = expf((float)(SEQ-1 - (k0 + tg)) * lnalpha);  // weight of row tg at iter 0

    float acc[2][8][4];
    #pragma unroll
    for (int i=0;i<2;i++)
        #pragma unroll
        for (int j=0;j<8;j++)
            #pragma unroll
            for (int r=0;r<4;r++) acc[i][j][r]=0.f;

    const bool dov = (mt == 0) && (wm == 0);
    float vacc[8];
    #pragma unroll
    for (int j=0;j<8;j++) vacc[j]=0.f;

    auto do_mma = [&](const float* As_, const float* Bs_, int kk, float wA, float wB){
        unsigned a[2][4];
        const float* Ar0 = As_ + (kk+tg)*SROW;
        const float* Ar1 = As_ + (kk+tg+4)*SROW;
        #pragma unroll
        for (int i=0;i<2;i++){
            const int mb = 32*wm + 16*i + gp;
            a[i][0] = tf32_rna(Ar0[mb]   * wA);
            a[i][1] = tf32_rna(Ar0[mb+8] * wA);
            a[i][2] = tf32_rna(Ar1[mb]   * wB);
            a[i][3] = tf32_rna(Ar1[mb+8] * wB);
        }
        const float* Br0 = Bs_ + (kk+tg)*SROW;
        const float* Br1 = Bs_ + (kk+tg+4)*SROW;
        #pragma unroll
        for (int j=0;j<8;j++){
            const int nb = 64*wn + 8*j + gp;
            float b0f = Br0[nb];
            float b1f = Br1[nb];
            if (dov) vacc[j] = fmaf(b0f, wA, fmaf(b1f, wB, vacc[j]));
            unsigned b0 = tf32_rna(b0f), b1 = tf32_rna(b1f);
            mma_tf32(acc[0][j], a[0], b0, b1);
            mma_tf32(acc[1][j], a[1], b0, b1);
        }
    };

    // prologue: 3 stages in flight
    issue_stage(0); CP_COMMIT();
    issue_stage(1); CP_COMMIT();
    issue_stage(2); CP_COMMIT();

    #pragma unroll 1
    for (int it = 0; it < NITER; ++it){
        CP_WAIT(2);
        __syncthreads();
        if (it + 3 < NITER) issue_stage(it + 3);
        CP_COMMIT();

        const float* St = sm1 + (it & (K1_STAGES-1)) * K1_STG_W;
        const float* As_ = St;
        const float* Bs_ = St + K1_OP_W;
        const float w0 = wt, w1 = wt*c4f, w2 = wt*c8f, w3 = wt*c12f;
        do_mma(As_, Bs_, 0, w0, w1);
        do_mma(As_, Bs_, 8, w2, w3);
        wt *= c16f;
    }

    // write partial M tile (unique writers, plain stores)
    float* Pp = g_P + (((size_t)(split*BATCH + b))*DIM + mt*TM)*DIM + nt*TN;
    #pragma unroll
    for (int i=0;i<2;i++){
        const int r = 32*wm + 16*i + gp;
        #pragma unroll
        for (int j=0;j<8;j++){
            const int cc = 64*wn + 8*j + 2*tg;
            *(float2*)&Pp[(size_t)r*DIM + cc]     = make_float2(acc[i][j][0], acc[i][j][1]);
            *(float2*)&Pp[(size_t)(r+8)*DIM + cc] = make_float2(acc[i][j][2], acc[i][j][3]);
        }
    }

    // partial v: reduce over tg (adjacent lanes) then store
    if (dov){
        #pragma unroll
        for (int j=0;j<8;j++){
            float v = vacc[j];
            v += __shfl_xor_sync(0xFFFFFFFFu, v, 1);
            v += __shfl_xor_sync(0xFFFFFFFFu, v, 2);
            if (tg == 0){
                g_V[((size_t)split*BATCH + b)*DIM + nt*TN + 64*wn + 8*j + gp] = v;
            }
        }
    }
}

// ---------------------------------------------------------------------------
// Kernel 2: C[b,s,d] = sum_d' W[s,d'] * M[b,d',d] + bias[s]*v[b,d]
// Both K-split partials of M are cp.async'd and summed at fragment-load time.
// ---------------------------------------------------------------------------
__global__ void __launch_bounds__(TPB,1)
k2_proj(const float* __restrict__ Wm, const float* __restrict__ bias, float* __restrict__ out)
{
    extern __shared__ float sm2[];

    const int tid  = threadIdx.x;
    const int lane = tid & 31;
    const int warp = tid >> 5;
    const int wm = warp & 3, wn = warp >> 2;
    const int tg = lane & 3;
    const int gp = lane >> 2;

    const int x  = blockIdx.x;
    const int nt = x & 3;
    const int mt = (x >> 2) & 3;
    const int b  = x >> 4;

    // A (W tile 128x16): chunk row am, float4 col ak4
    const int am  = tid >> 2;          // 0..63 (+64)
    const int ak4 = tid & 3;
    // B (M tile 16x128): chunk row bk, float4 col bn4
    const int bk  = tid >> 5;          // 0..7 (+8)
    const int bn4 = tid & 31;

    const float* Wg = Wm + (size_t)(mt*TM)*DIM;
    const unsigned sm_base = (unsigned)__cvta_generic_to_shared(sm2);
    const unsigned dA0  = sm_base + 4u*(am*AR2 + 4*ak4);
    const unsigned dB0  = sm_base + 4u*(K2_A_W + bk*SROW + 4*bn4);

    auto issue_stage = [&](int it){
        const unsigned so = (unsigned)(((unsigned)it % K2_STAGES) * K2_STG_W * 4);
        const float* pa = Wg + (size_t)am*DIM + it*TK2 + 4*ak4;
        cp16(dA0 + so, pa);
        cp16(dA0 + so + 4u*64*AR2, pa + (size_t)64*DIM);
        #pragma unroll
        for (int p=0;p<SPLITS;p++){
            const float* q = g_P + (((size_t)(p*BATCH + b))*DIM + it*TK2 + bk)*DIM + nt*TN + 4*bn4;
            const unsigned dB = dB0 + so + (unsigned)(4*p*K2_B_W);
            cp16(dB, q);
            cp16(dB + 4u*8*SROW, q + (size_t)8*DIM);
        }
    };

    float acc[2][8][4];
    #pragma unroll
    for (int i=0;i<2;i++)
        #pragma unroll
        for (int j=0;j<8;j++)
            #pragma unroll
            for (int r=0;r<4;r++) acc[i][j][r]=0.f;

    auto do_mma = [&](const float* As_, const float* B0_, const float* B1_, int kk){
        unsigned a[2][4];
        #pragma unroll
        for (int i=0;i<2;i++){
            const int mb = 32*wm + 16*i + gp;
            a[i][0] = tf32_rna(As_[(size_t)mb*AR2     + kk+tg  ]);
            a[i][1] = tf32_rna(As_[(size_t)(mb+8)*AR2 + kk+tg  ]);
            a[i][2] = tf32_rna(As_[(size_t)mb*AR2     + kk+tg+4]);
            a[i][3] = tf32_rna(As_[(size_t)(mb+8)*AR2 + kk+tg+4]);
        }
        const float* B0r0 = B0_ + (kk+tg)*SROW;
        const float* B0r1 = B0_ + (kk+tg+4)*SROW;
        const float* B1r0 = B1_ + (kk+tg)*SROW;
        const float* B1r1 = B1_ + (kk+tg+4)*SROW;
        #pragma unroll
        for (int j=0;j<8;j++){
            const int nb = 64*wn + 8*j + gp;
            unsigned b0 = tf32_rna(B0r0[nb] + B1r0[nb]);
            unsigned b1 = tf32_rna(B0r1[nb] + B1r1[nb]);
            mma_tf32(acc[0][j], a[0], b0, b1);
            mma_tf32(acc[1][j], a[1], b0, b1);
        }
    };

    // prologue: 2 stages in flight
    issue_stage(0); CP_COMMIT();
    issue_stage(1); CP_COMMIT();

    #pragma unroll 1
    for (int it = 0; it < NIT2; ++it){
        CP_WAIT(1);
        __syncthreads();
        if (it + 2 < NIT2) issue_stage(it + 2);
        CP_COMMIT();

        const float* St = sm2 + ((unsigned)it % K2_STAGES) * K2_STG_W;
        const float* As_ = St;
        const float* B0_ = St + K2_A_W;
        const float* B1_ = B0_ + K2_B_W;
        do_mma(As_, B0_, B1_, 0);
        do_mma(As_, B0_, B1_, 8);
    }

    // epilogue: + bias[s] * v[d]
    float* Co = out + (((size_t)b)*DIM + mt*TM)*DIM + nt*TN;
    float bi[2][2];
    #pragma unroll
    for (int i=0;i<2;i++){
        const int r = 32*wm + 16*i + gp;
        bi[i][0] = bias[mt*TM + r];
        bi[i][1] = bias[mt*TM + r + 8];
    }
    #pragma unroll
    for (int j=0;j<8;j++){
        const int cc = 64*wn + 8*j + 2*tg;
        const int cg = nt*TN + cc;
        float v0 = 0.f, v1 = 0.f;
        #pragma unroll
        for (int p=0;p<SPLITS;p++){
            const float* vp = g_V + ((size_t)p*BATCH + b)*DIM + cg;
            v0 += vp[0]; v1 += vp[1];
        }
        #pragma unroll
        for (int i=0;i<2;i++){
            const int r = 32*wm + 16*i + gp;
            *(float2*)&Co[(size_t)r*DIM + cc] =
                make_float2(acc[i][j][0] + bi[i][0]*v0, acc[i][j][1] + bi[i][0]*v1);
            *(float2*)&Co[(size_t)(r+8)*DIM + cc] =
                make_float2(acc[i][j][2] + bi[i][1]*v0, acc[i][j][3] + bi[i][1]*v1);
        }
    }
}

extern "C" void kernel_launch(void* const* d_in, const int* in_sizes, int n_in,
                              void* d_out, int out_size)
{
    const float* H    = (const float*)d_in[0];   // hidden_states (4,8192,512)
    const float* E    = (const float*)d_in[1];   // positional_encodings (4,8192,512)
    const float* Wm   = (const float*)d_in[2];   // W (512,512)
    const float* bias = (const float*)d_in[3];   // b (512,)
    float* out = (float*)d_out;                  // (4,512,512)

    cudaFuncSetAttribute(k1_outer, cudaFuncAttributeMaxDynamicSharedMemorySize, K1_SMEM_B);
    cudaFuncSetAttribute(k2_proj,  cudaFuncAttributeMaxDynamicSharedMemorySize, K2_SMEM_B);

    k1_outer<<<BATCH*4*4*SPLITS, TPB, K1_SMEM_B>>>(H, E);
    k2_proj<<<BATCH*4*4, TPB, K2_SMEM_B>>>(Wm, bias, out);
}

// round 3
// speedup vs baseline: 1.9758x; 1.3092x over previous
#include <cuda_runtime.h>
#include <math.h>

// Problem shape (fixed by the dataset)
#define BATCH 4
#define SEQ   8192
#define DIM   512

// Kernel 1 (outer-product GEMM): tiles 128x128, K-split 4, 4-stage cp.async
#define TM    128
#define TN    128
#define TK    16
#define SPLITS 4
#define KSPLIT (SEQ/SPLITS)
#define NITER (KSPLIT/TK)
#define SROW  136          // smem row stride (words): conflict-free frag reads
#define TPB   256
#define K1_STAGES 4
#define K1_OP_W   (TK*SROW)            // words per operand tile
#define K1_STG_W  (2*K1_OP_W)          // words per stage (A+B)
#define K1_SMEM_B (K1_STAGES*K1_STG_W*4)

// Kernel 2 (C = W @ M + bias*v): 64x128 tiles, K=512, 3-stage cp.async
#define TM2   64
#define TK2   16
#define NIT2  (DIM/TK2)
#define AR2   20           // smem row stride (words) for [m][k] W tile
#define K2_STAGES 3
#define K2_A_W   (TM2*AR2)             // 1280 words
#define K2_B_W   (TK2*SROW)            // 2176 words
#define K2_STG_W (K2_A_W + K2_B_W)     // 3456 words
#define K2_SMEM_B (K2_STAGES*K2_STG_W*4)

// Scratch
__device__ float g_P[(size_t)SPLITS*BATCH*DIM*DIM];   // 16 MB split partials
__device__ float g_M[(size_t)BATCH*DIM*DIM];          // 4 MB reduced M
__device__ float g_V[SPLITS*BATCH*DIM];
__device__ float g_v[BATCH*DIM];

__device__ __forceinline__ unsigned tf32_rna(float x){
    unsigned u; asm("cvt.rna.tf32.f32 %0, %1;" : "=r"(u) : "f"(x)); return u;
}
__device__ __forceinline__ void mma_tf32(float c[4], const unsigned a[4], unsigned b0, unsigned b1){
    asm("mma.sync.aligned.m16n8k8.row.col.f32.tf32.tf32.f32 "
        "{%0,%1,%2,%3},{%4,%5,%6,%7},{%8,%9},{%0,%1,%2,%3};"
        : "+f"(c[0]), "+f"(c[1]), "+f"(c[2]), "+f"(c[3])
        : "r"(a[0]), "r"(a[1]), "r"(a[2]), "r"(a[3]), "r"(b0), "r"(b1));
}
__device__ __forceinline__ void cp16(unsigned dst, const float* src){
    asm volatile("cp.async.cg.shared.global [%0], [%1], 16;\n" :: "r"(dst), "l"(src));
}
#define CP_COMMIT() asm volatile("cp.async.commit_group;\n" ::: "memory")
#define CP_WAIT(n)  asm volatile("cp.async.wait_group %0;\n" :: "n"(n) : "memory")

// ---------------------------------------------------------------------------
// Kernel 1: M partials (per K-split) + v partials
// ---------------------------------------------------------------------------
__global__ void __launch_bounds__(TPB,2)
k1_outer(const float* __restrict__ H, const float* __restrict__ E)
{
    extern __shared__ float sm1[];

    const int tid  = threadIdx.x;
    const int lane = tid & 31;
    const int warp = tid >> 5;
    const int wm = warp & 3, wn = warp >> 2;   // 4x2 warp grid -> warp tile 32x64
    const int tg = lane & 3;
    const int gp = lane >> 2;

    const int x     = blockIdx.x;
    const int split = x & (SPLITS-1);
    const int nt    = (x >> 2) & 3;
    const int mt    = (x >> 4) & 3;
    const int b     = x >> 6;

    const int k0 = split * KSPLIT;
    const float* Ag = H + ((size_t)b*SEQ + k0)*DIM + mt*TM;
    const float* Bg = E + ((size_t)b*SEQ + k0)*DIM + nt*TN;

    const int kr = tid >> 5;   // 0..7
    const int c4 = tid & 31;   // float4 column
    const float* Ap = Ag + (size_t)kr*DIM + 4*c4;
    const float* Bp = Bg + (size_t)kr*DIM + 4*c4;
    const size_t step = (size_t)TK*DIM;

    const unsigned sm_base = (unsigned)__cvta_generic_to_shared(sm1);
    const unsigned dA0 = sm_base + 4u*(kr*SROW + 4*c4);
    const unsigned dB0 = sm_base + 4u*(K1_OP_W + kr*SROW + 4*c4);

    auto issue_stage = [&](int it){
        const unsigned so = (unsigned)((it & (K1_STAGES-1)) * K1_STG_W * 4);
        const float* a = Ap + (size_t)it*step;
        const float* bb = Bp + (size_t)it*step;
        cp16(dA0 + so, a);
        cp16(dA0 + so + 4u*8*SROW, a + 8*DIM);
        cp16(dB0 + so, bb);
        cp16(dB0 + so + 4u*8*SROW, bb + 8*DIM);
    };

    // decay weights
    const float lnalpha = logf((float)0.9996165783279395);
    const float c4f  = expf(-4.0f*lnalpha);
    const float c8f  = expf(-8.0f*lnalpha);
    const float c12f = expf(-12.0f*lnalpha);
    const float c16f = expf(-16.0f*lnalpha);
    float wt = expf((float)(SEQ-1 - (k0 + tg)) * lnalpha);

    float acc[2][8][4];
    #pragma unroll
    for (int i=0;i<2;i++)
        #pragma unroll
        for (int j=0;j<8;j++)
            #pragma unroll
            for (int r=0;r<4;r++) acc[i][j][r]=0.f;

    const bool dov = (mt == 0) && (wm == 0);
    float vacc[8];
    #pragma unroll
    for (int j=0;j<8;j++) vacc[j]=0.f;

    auto do_mma = [&](const float* As_, const float* Bs_, int kk, float wA, float wB){
        unsigned a[2][4];
        const float* Ar0 = As_ + (kk+tg)*SROW;
        const float* Ar1 = As_ + (kk+tg+4)*SROW;
        #pragma unroll
        for (int i=0;i<2;i++){
            const int mb = 32*wm + 16*i + gp;
            a[i][0] = tf32_rna(Ar0[mb]   * wA);
            a[i][1] = tf32_rna(Ar0[mb+8] * wA);
            a[i][2] = tf32_rna(Ar1[mb]   * wB);
            a[i][3] = tf32_rna(Ar1[mb+8] * wB);
        }
        const float* Br0 = Bs_ + (kk+tg)*SROW;
        const float* Br1 = Bs_ + (kk+tg+4)*SROW;
        #pragma unroll
        for (int j=0;j<8;j++){
            const int nb = 64*wn + 8*j + gp;
            float b0f = Br0[nb];
            float b1f = Br1[nb];
            if (dov) vacc[j] = fmaf(b0f, wA, fmaf(b1f, wB, vacc[j]));
            unsigned b0 = tf32_rna(b0f), b1 = tf32_rna(b1f);
            mma_tf32(acc[0][j], a[0], b0, b1);
            mma_tf32(acc[1][j], a[1], b0, b1);
        }
    };

    issue_stage(0); CP_COMMIT();
    issue_stage(1); CP_COMMIT();
    issue_stage(2); CP_COMMIT();

    #pragma unroll 1
    for (int it = 0; it < NITER; ++it){
        CP_WAIT(2);
        __syncthreads();
        if (it + 3 < NITER) issue_stage(it + 3);
        CP_COMMIT();

        const float* St = sm1 + (it & (K1_STAGES-1)) * K1_STG_W;
        const float w0 = wt, w1 = wt*c4f, w2 = wt*c8f, w3 = wt*c12f;
        do_mma(St, St + K1_OP_W, 0, w0, w1);
        do_mma(St, St + K1_OP_W, 8, w2, w3);
        wt *= c16f;
    }

    float* Pp = g_P + (((size_t)(split*BATCH + b))*DIM + mt*TM)*DIM + nt*TN;
    #pragma unroll
    for (int i=0;i<2;i++){
        const int r = 32*wm + 16*i + gp;
        #pragma unroll
        for (int j=0;j<8;j++){
            const int cc = 64*wn + 8*j + 2*tg;
            *(float2*)&Pp[(size_t)r*DIM + cc]     = make_float2(acc[i][j][0], acc[i][j][1]);
            *(float2*)&Pp[(size_t)(r+8)*DIM + cc] = make_float2(acc[i][j][2], acc[i][j][3]);
        }
    }

    if (dov){
        #pragma unroll
        for (int j=0;j<8;j++){
            float v = vacc[j];
            v += __shfl_xor_sync(0xFFFFFFFFu, v, 1);
            v += __shfl_xor_sync(0xFFFFFFFFu, v, 2);
            if (tg == 0){
                g_V[((size_t)split*BATCH + b)*DIM + nt*TN + 64*wn + 8*j + gp] = v;
            }
        }
    }
}

// ---------------------------------------------------------------------------
// Reduction: g_M = sum_p g_P[p], g_v = sum_p g_V[p]
// ---------------------------------------------------------------------------
__global__ void __launch_bounds__(256)
kred()
{
    const int gid = blockIdx.x*blockDim.x + threadIdx.x;
    const int nth = gridDim.x*blockDim.x;
    const size_t tot4 = (size_t)BATCH*DIM*DIM/4;      // 262144 float4
    const size_t pstride = tot4;                       // float4 stride per split
    const float4* Pin = (const float4*)g_P;
    float4* Mout = (float4*)g_M;
    for (size_t i = gid; i < tot4; i += nth){
        float4 s = Pin[i];
        #pragma unroll
        for (int p=1;p<SPLITS;p++){
            float4 t = Pin[i + p*pstride];
            s.x+=t.x; s.y+=t.y; s.z+=t.z; s.w+=t.w;
        }
        Mout[i] = s;
    }
    if (gid < BATCH*DIM/4){
        const float4* Vin = (const float4*)g_V;
        float4 s = Vin[gid];
        #pragma unroll
        for (int p=1;p<SPLITS;p++){
            float4 t = Vin[gid + p*(BATCH*DIM/4)];
            s.x+=t.x; s.y+=t.y; s.z+=t.z; s.w+=t.w;
        }
        ((float4*)g_v)[gid] = s;
    }
}

// ---------------------------------------------------------------------------
// Kernel 2: C[b,s,d] = sum_d' W[s,d'] * M[b,d',d] + bias[s]*v[b,d]
// 64x128 output tiles, warp tile 32x32 (2x4 warp grid)
// ---------------------------------------------------------------------------
__global__ void __launch_bounds__(TPB,2)
k2_proj(const float* __restrict__ Wm, const float* __restrict__ bias, float* __restrict__ out)
{
    extern __shared__ float sm2[];

    const int tid  = threadIdx.x;
    const int lane = tid & 31;
    const int warp = tid >> 5;
    const int wm = warp & 1, wn = warp >> 1;   // 2x4 warp grid, warp tile 32x32
    const int tg = lane & 3;
    const int gp = lane >> 2;

    const int x  = blockIdx.x;
    const int nt = x & 3;          // 4 n-tiles of 128
    const int mt = (x >> 2) & 7;   // 8 m-tiles of 64
    const int b  = x >> 5;

    // A (W tile 64x16): one float4 per thread
    const int am  = tid >> 2;          // 0..63
    const int ak4 = tid & 3;
    // B (M tile 16x128): two float4 per thread
    const int bk  = tid >> 5;          // 0..7 (+8)
    const int bn4 = tid & 31;

    const float* Wg = Wm + (size_t)(mt*TM2)*DIM;
    const unsigned sm_base = (unsigned)__cvta_generic_to_shared(sm2);
    const unsigned dA0  = sm_base + 4u*(am*AR2 + 4*ak4);
    const unsigned dB0  = sm_base + 4u*(K2_A_W + bk*SROW + 4*bn4);

    auto issue_stage = [&](int it){
        const unsigned so = (unsigned)(((unsigned)it % K2_STAGES) * K2_STG_W * 4);
        cp16(dA0 + so, Wg + (size_t)am*DIM + it*TK2 + 4*ak4);
        const float* q = g_M + ((size_t)b*DIM + it*TK2 + bk)*DIM + nt*TN + 4*bn4;
        cp16(dB0 + so, q);
        cp16(dB0 + so + 4u*8*SROW, q + (size_t)8*DIM);
    };

    float acc[2][4][4];
    #pragma unroll
    for (int i=0;i<2;i++)
        #pragma unroll
        for (int j=0;j<4;j++)
            #pragma unroll
            for (int r=0;r<4;r++) acc[i][j][r]=0.f;

    auto do_mma = [&](const float* As_, const float* Bs_, int kk){
        unsigned a[2][4];
        #pragma unroll
        for (int i=0;i<2;i++){
            const int mb = 32*wm + 16*i + gp;
            a[i][0] = tf32_rna(As_[(size_t)mb*AR2     + kk+tg  ]);
            a[i][1] = tf32_rna(As_[(size_t)(mb+8)*AR2 + kk+tg  ]);
            a[i][2] = tf32_rna(As_[(size_t)mb*AR2     + kk+tg+4]);
            a[i][3] = tf32_rna(As_[(size_t)(mb+8)*AR2 + kk+tg+4]);
        }
        const float* Br0 = Bs_ + (kk+tg)*SROW;
        const float* Br1 = Bs_ + (kk+tg+4)*SROW;
        #pragma unroll
        for (int j=0;j<4;j++){
            const int nb = 32*wn + 8*j + gp;
            unsigned b0 = tf32_rna(Br0[nb]);
            unsigned b1 = tf32_rna(Br1[nb]);
            mma_tf32(acc[0][j], a[0], b0, b1);
            mma_tf32(acc[1][j], a[1], b0, b1);
        }
    };

    issue_stage(0); CP_COMMIT();
    issue_stage(1); CP_COMMIT();

    #pragma unroll 1
    for (int it = 0; it < NIT2; ++it){
        CP_WAIT(1);
        __syncthreads();
        if (it + 2 < NIT2) issue_stage(it + 2);
        CP_COMMIT();

        const float* St = sm2 + ((unsigned)it % K2_STAGES) * K2_STG_W;
        do_mma(St, St + K2_A_W, 0);
        do_mma(St, St + K2_A_W, 8);
    }

    // epilogue: + bias[s] * v[d]
    float* Co = out + (((size_t)b)*DIM + mt*TM2)*DIM + nt*TN;
    float bi[2][2];
    #pragma unroll
    for (int i=0;i<2;i++){
        const int r = 32*wm + 16*i + gp;
        bi[i][0] = bias[mt*TM2 + r];
        bi[i][1] = bias[mt*TM2 + r + 8];
    }
    #pragma unroll
    for (int j=0;j<4;j++){
        const int cc = 32*wn + 8*j + 2*tg;
        const float* vp = g_v + (size_t)b*DIM + nt*TN + cc;
        float v0 = vp[0], v1 = vp[1];
        #pragma unroll
        for (int i=0;i<2;i++){
            const int r = 32*wm + 16*i + gp;
            *(float2*)&Co[(size_t)r*DIM + cc] =
                make_float2(acc[i][j][0] + bi[i][0]*v0, acc[i][j][1] + bi[i][0]*v1);
            *(float2*)&Co[(size_t)(r+8)*DIM + cc] =
                make_float2(acc[i][j][2] + bi[i][1]*v0, acc[i][j][3] + bi[i][1]*v1);
        }
    }
}

extern "C" void kernel_launch(void* const* d_in, const int* in_sizes, int n_in,
                              void* d_out, int out_size)
{
    const float* H    = (const float*)d_in[0];   // hidden_states (4,8192,512)
    const float* E    = (const float*)d_in[1];   // positional_encodings (4,8192,512)
    const float* Wm   = (const float*)d_in[2];   // W (512,512)
    const float* bias = (const float*)d_in[3];   // b (512,)
    float* out = (float*)d_out;                  // (4,512,512)

    cudaFuncSetAttribute(k1_outer, cudaFuncAttributeMaxDynamicSharedMemorySize, K1_SMEM_B);
    cudaFuncSetAttribute(k2_proj,  cudaFuncAttributeMaxDynamicSharedMemorySize, K2_SMEM_B);

    k1_outer<<<BATCH*4*4*SPLITS, TPB, K1_SMEM_B>>>(H, E);
    kred<<<256, 256>>>();
    k2_proj<<<BATCH*8*4, TPB, K2_SMEM_B>>>(Wm, bias, out);
}

// round 5
// speedup vs baseline: 1.9771x; 1.0006x over previous
#include <cuda_runtime.h>
#include <math.h>

// Problem shape (fixed by the dataset)
#define BATCH 4
#define SEQ   8192
#define DIM   512

// Kernel 1 (outer-product GEMM): tiles 128x128, K-split 4, 4-stage cp.async
#define TM    128
#define TN    128
#define TK    16
#define SPLITS 4
#define KSPLIT (SEQ/SPLITS)
#define NITER (KSPLIT/TK)
#define SROW  136          // smem row stride (words): conflict-free frag reads
#define TPB   256
#define K1_STAGES 4
#define K1_OP_W   (TK*SROW)            // words per operand tile
#define K1_STG_W  (2*K1_OP_W)          // words per stage (A+B)
#define K1_SMEM_B (K1_STAGES*K1_STG_W*4)

// Kernel 2 (C = W @ M + bias*v): 64x128 tiles, K=512, 3-stage cp.async
#define TM2   64
#define TK2   16
#define NIT2  (DIM/TK2)
#define AR2   20           // smem row stride (words) for [m][k] W tile
#define K2_STAGES 3
#define K2_A_W   (TM2*AR2)             // 1280 words
#define K2_B_W   (TK2*SROW)            // 2176 words
#define K2_STG_W (K2_A_W + K2_B_W)     // 3456 words
#define K2_SMEM_B (K2_STAGES*K2_STG_W*4)

// Scratch
__device__ float g_P[(size_t)SPLITS*BATCH*DIM*DIM];   // 16 MB split partials
__device__ float g_M[(size_t)BATCH*DIM*DIM];          // 4 MB reduced M
__device__ float g_V[SPLITS*BATCH*DIM];
__device__ float g_v[BATCH*DIM];

__device__ __forceinline__ unsigned tf32_rna(float x){
    unsigned u; asm("cvt.rna.tf32.f32 %0, %1;" : "=r"(u) : "f"(x)); return u;
}
__device__ __forceinline__ void mma_tf32(float c[4], const unsigned a[4], unsigned b0, unsigned b1){
    asm("mma.sync.aligned.m16n8k8.row.col.f32.tf32.tf32.f32 "
        "{%0,%1,%2,%3},{%4,%5,%6,%7},{%8,%9},{%0,%1,%2,%3};"
        : "+f"(c[0]), "+f"(c[1]), "+f"(c[2]), "+f"(c[3])
        : "r"(a[0]), "r"(a[1]), "r"(a[2]), "r"(a[3]), "r"(b0), "r"(b1));
}
__device__ __forceinline__ void cp16(unsigned dst, const float* src){
    asm volatile("cp.async.cg.shared.global [%0], [%1], 16;\n" :: "r"(dst), "l"(src));
}
#define CP_COMMIT() asm volatile("cp.async.commit_group;\n" ::: "memory")
#define CP_WAIT(n)  asm volatile("cp.async.wait_group %0;\n" :: "n"(n) : "memory")

// ---------------------------------------------------------------------------
// Kernel 1: M partials (per K-split) + v partials
// ---------------------------------------------------------------------------
__global__ void __launch_bounds__(TPB,2)
k1_outer(const float* __restrict__ H, const float* __restrict__ E)
{
    extern __shared__ float sm1[];

    const int tid  = threadIdx.x;
    const int lane = tid & 31;
    const int warp = tid >> 5;
    const int wm = warp & 3, wn = warp >> 2;   // 4x2 warp grid -> warp tile 32x64
    const int tg = lane & 3;
    const int gp = lane >> 2;

    const int x     = blockIdx.x;
    const int split = x & (SPLITS-1);
    const int nt    = (x >> 2) & 3;
    const int mt    = (x >> 4) & 3;
    const int b     = x >> 6;

    const int k0 = split * KSPLIT;
    const float* Ag = H + ((size_t)b*SEQ + k0)*DIM + mt*TM;
    const float* Bg = E + ((size_t)b*SEQ + k0)*DIM + nt*TN;

    const int kr = tid >> 5;   // 0..7
    const int c4 = tid & 31;   // float4 column
    const float* Ap = Ag + (size_t)kr*DIM + 4*c4;
    const float* Bp = Bg + (size_t)kr*DIM + 4*c4;
    const size_t step = (size_t)TK*DIM;

    const unsigned sm_base = (unsigned)__cvta_generic_to_shared(sm1);
    const unsigned dA0 = sm_base + 4u*(kr*SROW + 4*c4);
    const unsigned dB0 = sm_base + 4u*(K1_OP_W + kr*SROW + 4*c4);

    auto issue_stage = [&](int it){
        const unsigned so = (unsigned)((it & (K1_STAGES-1)) * K1_STG_W * 4);
        const float* a = Ap + (size_t)it*step;
        const float* bb = Bp + (size_t)it*step;
        cp16(dA0 + so, a);
        cp16(dA0 + so + 4u*8*SROW, a + 8*DIM);
        cp16(dB0 + so, bb);
        cp16(dB0 + so + 4u*8*SROW, bb + 8*DIM);
    };

    // decay weights
    const float lnalpha = logf((float)0.9996165783279395);
    const float c4f  = expf(-4.0f*lnalpha);
    const float c8f  = expf(-8.0f*lnalpha);
    const float c12f = expf(-12.0f*lnalpha);
    const float c16f = expf(-16.0f*lnalpha);
    float wt = expf((float)(SEQ-1 - (k0 + tg)) * lnalpha);

    float acc[2][8][4];
    #pragma unroll
    for (int i=0;i<2;i++)
        #pragma unroll
        for (int j=0;j<8;j++)
            #pragma unroll
            for (int r=0;r<4;r++) acc[i][j][r]=0.f;

    const bool dov = (mt == 0) && (wm == 0);
    float vacc[8];
    #pragma unroll
    for (int j=0;j<8;j++) vacc[j]=0.f;

    auto do_mma = [&](const float* As_, const float* Bs_, int kk, float wA, float wB){
        unsigned a[2][4];
        const float* Ar0 = As_ + (kk+tg)*SROW;
        const float* Ar1 = As_ + (kk+tg+4)*SROW;
        #pragma unroll
        for (int i=0;i<2;i++){
            const int mb = 32*wm + 16*i + gp;
            a[i][0] = tf32_rna(Ar0[mb]   * wA);
            a[i][1] = tf32_rna(Ar0[mb+8] * wA);
            a[i][2] = tf32_rna(Ar1[mb]   * wB);
            a[i][3] = tf32_rna(Ar1[mb+8] * wB);
        }
        const float* Br0 = Bs_ + (kk+tg)*SROW;
        const float* Br1 = Bs_ + (kk+tg+4)*SROW;
        #pragma unroll
        for (int j=0;j<8;j++){
            const int nb = 64*wn + 8*j + gp;
            float b0f = Br0[nb];
            float b1f = Br1[nb];
            if (dov) vacc[j] = fmaf(b0f, wA, fmaf(b1f, wB, vacc[j]));
            unsigned b0 = tf32_rna(b0f), b1 = tf32_rna(b1f);
            mma_tf32(acc[0][j], a[0], b0, b1);
            mma_tf32(acc[1][j], a[1], b0, b1);
        }
    };

    issue_stage(0); CP_COMMIT();
    issue_stage(1); CP_COMMIT();
    issue_stage(2); CP_COMMIT();

    #pragma unroll 1
    for (int it = 0; it < NITER; ++it){
        CP_WAIT(2);
        __syncthreads();
        if (it + 3 < NITER) issue_stage(it + 3);
        CP_COMMIT();

        const float* St = sm1 + (it & (K1_STAGES-1)) * K1_STG_W;
        const float w0 = wt, w1 = wt*c4f, w2 = wt*c8f, w3 = wt*c12f;
        do_mma(St, St + K1_OP_W, 0, w0, w1);
        do_mma(St, St + K1_OP_W, 8, w2, w3);
        wt *= c16f;
    }

    float* Pp = g_P + (((size_t)(split*BATCH + b))*DIM + mt*TM)*DIM + nt*TN;
    #pragma unroll
    for (int i=0;i<2;i++){
        const int r = 32*wm + 16*i + gp;
        #pragma unroll
        for (int j=0;j<8;j++){
            const int cc = 64*wn + 8*j + 2*tg;
            *(float2*)&Pp[(size_t)r*DIM + cc]     = make_float2(acc[i][j][0], acc[i][j][1]);
            *(float2*)&Pp[(size_t)(r+8)*DIM + cc] = make_float2(acc[i][j][2], acc[i][j][3]);
        }
    }

    if (dov){
        #pragma unroll
        for (int j=0;j<8;j++){
            float v = vacc[j];
            v += __shfl_xor_sync(0xFFFFFFFFu, v, 1);
            v += __shfl_xor_sync(0xFFFFFFFFu, v, 2);
            if (tg == 0){
                g_V[((size_t)split*BATCH + b)*DIM + nt*TN + 64*wn + 8*j + gp] = v;
            }
        }
    }
}

// ---------------------------------------------------------------------------
// Reduction: g_M = sum_p g_P[p], g_v = sum_p g_V[p]
// ---------------------------------------------------------------------------
__global__ void __launch_bounds__(256)
kred()
{
    const int gid = blockIdx.x*blockDim.x + threadIdx.x;
    const int nth = gridDim.x*blockDim.x;
    const size_t tot4 = (size_t)BATCH*DIM*DIM/4;      // 262144 float4
    const size_t pstride = tot4;                       // float4 stride per split
    const float4* Pin = (const float4*)g_P;
    float4* Mout = (float4*)g_M;
    for (size_t i = gid; i < tot4; i += nth){
        float4 s = Pin[i];
        #pragma unroll
        for (int p=1;p<SPLITS;p++){
            float4 t = Pin[i + p*pstride];
            s.x+=t.x; s.y+=t.y; s.z+=t.z; s.w+=t.w;
        }
        Mout[i] = s;
    }
    if (gid < BATCH*DIM/4){
        const float4* Vin = (const float4*)g_V;
        float4 s = Vin[gid];
        #pragma unroll
        for (int p=1;p<SPLITS;p++){
            float4 t = Vin[gid + p*(BATCH*DIM/4)];
            s.x+=t.x; s.y+=t.y; s.z+=t.z; s.w+=t.w;
        }
        ((float4*)g_v)[gid] = s;
    }
}

// ---------------------------------------------------------------------------
// Kernel 2: C[b,s,d] = sum_d' W[s,d'] * M[b,d',d] + bias[s]*v[b,d]
// 64x128 output tiles, warp tile 32x32 (2x4 warp grid)
// ---------------------------------------------------------------------------
__global__ void __launch_bounds__(TPB,2)
k2_proj(const float* __restrict__ Wm, const float* __restrict__ bias, float* __restrict__ out)
{
    extern __shared__ float sm2[];

    const int tid  = threadIdx.x;
    const int lane = tid & 31;
    const int warp = tid >> 5;
    const int wm = warp & 1, wn = warp >> 1;   // 2x4 warp grid, warp tile 32x32
    const int tg = lane & 3;
    const int gp = lane >> 2;

    const int x  = blockIdx.x;
    const int nt = x & 3;          // 4 n-tiles of 128
    const int mt = (x >> 2) & 7;   // 8 m-tiles of 64
    const int b  = x >> 5;

    // A (W tile 64x16): one float4 per thread
    const int am  = tid >> 2;          // 0..63
    const int ak4 = tid & 3;
    // B (M tile 16x128): two float4 per thread
    const int bk  = tid >> 5;          // 0..7 (+8)
    const int bn4 = tid & 31;

    const float* Wg = Wm + (size_t)(mt*TM2)*DIM;
    const unsigned sm_base = (unsigned)__cvta_generic_to_shared(sm2);
    const unsigned dA0  = sm_base + 4u*(am*AR2 + 4*ak4);
    const unsigned dB0  = sm_base + 4u*(K2_A_W + bk*SROW + 4*bn4);

    auto issue_stage = [&](int it){
        const unsigned so = (unsigned)(((unsigned)it % K2_STAGES) * K2_STG_W * 4);
        cp16(dA0 + so, Wg + (size_t)am*DIM + it*TK2 + 4*ak4);
        const float* q = g_M + ((size_t)b*DIM + it*TK2 + bk)*DIM + nt*TN + 4*bn4;
        cp16(dB0 + so, q);
        cp16(dB0 + so + 4u*8*SROW, q + (size_t)8*DIM);
    };

    float acc[2][4][4];
    #pragma unroll
    for (int i=0;i<2;i++)
        #pragma unroll
        for (int j=0;j<4;j++)
            #pragma unroll
            for (int r=0;r<4;r++) acc[i][j][r]=0.f;

    auto do_mma = [&](const float* As_, const float* Bs_, int kk){
        unsigned a[2][4];
        #pragma unroll
        for (int i=0;i<2;i++){
            const int mb = 32*wm + 16*i + gp;
            a[i][0] = tf32_rna(As_[(size_t)mb*AR2     + kk+tg  ]);
            a[i][1] = tf32_rna(As_[(size_t)(mb+8)*AR2 + kk+tg  ]);
            a[i][2] = tf32_rna(As_[(size_t)mb*AR2     + kk+tg+4]);
            a[i][3] = tf32_rna(As_[(size_t)(mb+8)*AR2 + kk+tg+4]);
        }
        const float* Br0 = Bs_ + (kk+tg)*SROW;
        const float* Br1 = Bs_ + (kk+tg+4)*SROW;
        #pragma unroll
        for (int j=0;j<4;j++){
            const int nb = 32*wn + 8*j + gp;
            unsigned b0 = tf32_rna(Br0[nb]);
            unsigned b1 = tf32_rna(Br1[nb]);
            mma_tf32(acc[0][j], a[0], b0, b1);
            mma_tf32(acc[1][j], a[1], b0, b1);
        }
    };

    issue_stage(0); CP_COMMIT();
    issue_stage(1); CP_COMMIT();

    #pragma unroll 1
    for (int it = 0; it < NIT2; ++it){
        CP_WAIT(1);
        __syncthreads();
        if (it + 2 < NIT2) issue_stage(it + 2);
        CP_COMMIT();

        const float* St = sm2 + ((unsigned)it % K2_STAGES) * K2_STG_W;
        do_mma(St, St + K2_A_W, 0);
        do_mma(St, St + K2_A_W, 8);
    }

    // epilogue: + bias[s] * v[d]
    float* Co = out + (((size_t)b)*DIM + mt*TM2)*DIM + nt*TN;
    float bi[2][2];
    #pragma unroll
    for (int i=0;i<2;i++){
        const int r = 32*wm + 16*i + gp;
        bi[i][0] = bias[mt*TM2 + r];
        bi[i][1] = bias[mt*TM2 + r + 8];
    }
    #pragma unroll
    for (int j=0;j<4;j++){
        const int cc = 32*wn + 8*j + 2*tg;
        const float* vp = g_v + (size_t)b*DIM + nt*TN + cc;
        float v0 = vp[0], v1 = vp[1];
        #pragma unroll
        for (int i=0;i<2;i++){
            const int r = 32*wm + 16*i + gp;
            *(float2*)&Co[(size_t)r*DIM + cc] =
                make_float2(acc[i][j][0] + bi[i][0]*v0, acc[i][j][1] + bi[i][0]*v1);
            *(float2*)&Co[(size_t)(r+8)*DIM + cc] =
                make_float2(acc[i][j][2] + bi[i][1]*v0, acc[i][j][3] + bi[i][1]*v1);
        }
    }
}

extern "C" void kernel_launch(void* const* d_in, const int* in_sizes, int n_in,
                              void* d_out, int out_size)
{
    const float* H    = (const float*)d_in[0];   // hidden_states (4,8192,512)
    const float* E    = (const float*)d_in[1];   // positional_encodings (4,8192,512)
    const float* Wm   = (const float*)d_in[2];   // W (512,512)
    const float* bias = (const float*)d_in[3];   // b (512,)
    float* out = (float*)d_out;                  // (4,512,512)

    cudaFuncSetAttribute(k1_outer, cudaFuncAttributeMaxDynamicSharedMemorySize, K1_SMEM_B);
    cudaFuncSetAttribute(k2_proj,  cudaFuncAttributeMaxDynamicSharedMemorySize, K2_SMEM_B);

    k1_outer<<<BATCH*4*4*SPLITS, TPB, K1_SMEM_B>>>(H, E);
    kred<<<256, 256>>>();
    k2_proj<<<BATCH*8*4, TPB, K2_SMEM_B>>>(Wm, bias, out);
}

// round 7
// speedup vs baseline: 2.4474x; 1.2379x over previous
#include <cuda_runtime.h>
#include <math.h>
#include <cstdint>

#define BATCH 4
#define SEQ   8192
#define DIM   512

// ---- Kernel 1: 128x128 tiles, K-split 4, fp16 m16n8k16, K=16/iter ----
#define TM    128
#define TN    128
#define TK    16
#define SPLITS 4
#define KSPLIT (SEQ/SPLITS)
#define NITER (KSPLIT/TK)     // 128
#define PAD1  136             // uint32 row stride (k-pair rows)

// ---- Kernel 2: 64x128 tiles ----
#define TM2   64
#define TK2   16
#define NIT2  (DIM/TK2)       // 32
#define AR2   12              // uint32 row stride for [m][kp] W tile

__device__ float    g_P[(size_t)SPLITS*BATCH*DIM*DIM];   // 16 MB f32 split partials
__device__ unsigned g_Mh[(size_t)BATCH*(DIM/2)*DIM];     // 4 MB f16x2-packed M
__device__ float    g_V[SPLITS*BATCH*DIM];
__device__ float    g_v[BATCH*DIM];

// pack two f32 -> f16x2 (lo = first arg, hi = second arg)
__device__ __forceinline__ unsigned pkh(float lo, float hi){
    unsigned u; asm("cvt.rn.f16x2.f32 %0, %1, %2;" : "=r"(u) : "f"(hi), "f"(lo)); return u;
}
__device__ __forceinline__ void mma_f16(float c[4], const unsigned a[4], unsigned b0, unsigned b1){
    asm("mma.sync.aligned.m16n8k16.row.col.f32.f16.f16.f32 "
        "{%0,%1,%2,%3},{%4,%5,%6,%7},{%8,%9},{%0,%1,%2,%3};"
        : "+f"(c[0]), "+f"(c[1]), "+f"(c[2]), "+f"(c[3])
        : "r"(a[0]), "r"(a[1]), "r"(a[2]), "r"(a[3]), "r"(b0), "r"(b1));
}

// ---------------------------------------------------------------------------
// Kernel 1: g_P[split,b][m][n] = sum_t w_t H[t,m] E[t,n];  g_V (mt==0 CTAs)
// SMEM tiles hold f16x2 pairs along k: [k/2][feature], producer converts.
// ---------------------------------------------------------------------------
__global__ void __launch_bounds__(256,2)
k1_outer(const float* __restrict__ H, const float* __restrict__ E)
{
    __shared__ unsigned As[2][8][PAD1];
    __shared__ unsigned Bs[2][8][PAD1];
    __shared__ float vsm[256*4];

    const int tid  = threadIdx.x;
    const int lane = tid & 31;
    const int warp = tid >> 5;
    const int wm = warp & 3, wn = warp >> 2;   // warp tile 32m x 64n
    const int tg = lane & 3;
    const int gp = lane >> 2;

    const int x     = blockIdx.x;
    const int split = x & 3;
    const int nt    = (x >> 2) & 3;
    const int mt    = (x >> 4) & 3;
    const int b     = x >> 6;
    const int k0    = split * KSPLIT;

    // producer coords: kr = k-pair row (covers global rows k0+16it+2kr, +2kr+1)
    const int kr = tid >> 5;
    const int c4 = tid & 31;
    const float* Ap = H + ((size_t)(b*SEQ + k0 + 2*kr))*DIM + mt*TM + 4*c4;
    const float* Bp = E + ((size_t)(b*SEQ + k0 + 2*kr))*DIM + nt*TN + 4*c4;
    const size_t step = (size_t)TK*DIM;

    const float lnalpha = logf((float)0.9996165783279395);
    const float c1f  = expf(-1.0f*lnalpha);
    const float c16f = expf(-16.0f*lnalpha);
    float wt = expf((float)(SEQ-1 - (k0 + 2*kr)) * lnalpha);   // weight of even row, iter 0

    float acc[2][8][4];
    #pragma unroll
    for (int i=0;i<2;i++)
        #pragma unroll
        for (int j=0;j<8;j++)
            #pragma unroll
            for (int r=0;r<4;r++) acc[i][j][r]=0.f;

    const bool dov = (mt == 0);
    float vacc[4] = {0.f,0.f,0.f,0.f};

    float4 q0[4], q1[4];     // [a_even, a_odd, b_even, b_odd]

    auto ldq = [&](int it, float4* q){
        const float* ap = Ap + (size_t)it*step;
        const float* bp = Bp + (size_t)it*step;
        q[0] = *(const float4*)(ap);
        q[1] = *(const float4*)(ap + DIM);
        q[2] = *(const float4*)(bp);
        q[3] = *(const float4*)(bp + DIM);
    };
    auto stq = [&](int buf, const float4* q){
        const float w0 = wt, w1 = wt*c1f;
        uint4 ua;
        ua.x = pkh(q[0].x, q[1].x);
        ua.y = pkh(q[0].y, q[1].y);
        ua.z = pkh(q[0].z, q[1].z);
        ua.w = pkh(q[0].w, q[1].w);
        *(uint4*)&As[buf][kr][4*c4] = ua;
        float s0x=q[2].x*w0, s0y=q[2].y*w0, s0z=q[2].z*w0, s0w=q[2].w*w0;
        float s1x=q[3].x*w1, s1y=q[3].y*w1, s1z=q[3].z*w1, s1w=q[3].w*w1;
        if (dov){ vacc[0]+=s0x+s1x; vacc[1]+=s0y+s1y; vacc[2]+=s0z+s1z; vacc[3]+=s0w+s1w; }
        uint4 ub;
        ub.x = pkh(s0x, s1x);
        ub.y = pkh(s0y, s1y);
        ub.z = pkh(s0z, s1z);
        ub.w = pkh(s0w, s1w);
        *(uint4*)&Bs[buf][kr][4*c4] = ub;
        wt *= c16f;
    };
    auto do_mma = [&](int buf){
        unsigned a[2][4];
        const unsigned* Ar0 = As[buf][tg];
        const unsigned* Ar4 = As[buf][tg+4];
        #pragma unroll
        for (int i=0;i<2;i++){
            const int mb = 32*wm + 16*i + gp;
            a[i][0] = Ar0[mb];
            a[i][1] = Ar0[mb+8];
            a[i][2] = Ar4[mb];
            a[i][3] = Ar4[mb+8];
        }
        const unsigned* Br0 = Bs[buf][tg];
        const unsigned* Br4 = Bs[buf][tg+4];
        #pragma unroll
        for (int j=0;j<8;j++){
            const int nb = 64*wn + 8*j + gp;
            unsigned b0 = Br0[nb];
            unsigned b1 = Br4[nb];
            mma_f16(acc[0][j], a[0], b0, b1);
            mma_f16(acc[1][j], a[1], b0, b1);
        }
    };

    // prologue: q0 <- it0, store it0; q1 <- it1
    ldq(0, q0);
    stq(0, q0);
    ldq(1, q1);
    __syncthreads();

    #pragma unroll 1
    for (int it = 0; it < NITER; it += 2){
        // parity 0: consume buf0; q0 free -> prefetch it+2; q1 holds it+1 -> store buf1
        if (it + 2 < NITER) ldq(it + 2, q0);
        if (it + 1 < NITER) stq(1, q1);
        do_mma(0);
        __syncthreads();
        // parity 1: consume buf1; q1 free -> prefetch it+3; q0 holds it+2 -> store buf0
        if (it + 3 < NITER) ldq(it + 3, q1);
        if (it + 2 < NITER) stq(0, q0);
        do_mma(1);
        __syncthreads();
    }

    // write f32 partial tile
    float* Pp = g_P + (((size_t)(split*BATCH + b))*DIM + mt*TM)*DIM + nt*TN;
    #pragma unroll
    for (int i=0;i<2;i++){
        const int r = 32*wm + 16*i + gp;
        #pragma unroll
        for (int j=0;j<8;j++){
            const int cc = 64*wn + 8*j + 2*tg;
            *(float2*)&Pp[(size_t)r*DIM + cc]     = make_float2(acc[i][j][0], acc[i][j][1]);
            *(float2*)&Pp[(size_t)(r+8)*DIM + cc] = make_float2(acc[i][j][2], acc[i][j][3]);
        }
    }

    // v partial: reduce over kr groups (threads stride 32)
    if (dov){
        vsm[tid*4+0]=vacc[0]; vsm[tid*4+1]=vacc[1]; vsm[tid*4+2]=vacc[2]; vsm[tid*4+3]=vacc[3];
        __syncthreads();
        if (tid < 32){
            float s0=0.f,s1=0.f,s2=0.f,s3=0.f;
            #pragma unroll
            for (int r=0;r<8;r++){
                const float* p = vsm + ((r<<5) + tid)*4;
                s0+=p[0]; s1+=p[1]; s2+=p[2]; s3+=p[3];
            }
            float* vp = g_V + ((size_t)split*BATCH + b)*DIM + nt*TN + 4*tid;
            vp[0]=s0; vp[1]=s1; vp[2]=s2; vp[3]=s3;
        }
    }
}

// ---------------------------------------------------------------------------
// Reduction: g_Mh[b][kp][d] = pack_f16x2( sum_p P[2kp][d], sum_p P[2kp+1][d] )
//            g_v = sum_p g_V
// ---------------------------------------------------------------------------
__global__ void __launch_bounds__(256)
kred()
{
    const int gid = blockIdx.x*blockDim.x + threadIdx.x;   // 131072 items
    const int d4 = gid & 127;
    const int kp = (gid >> 7) & 255;
    const int b  = gid >> 15;

    const size_t pstride = (size_t)BATCH*DIM*DIM;
    const float* base = g_P + ((size_t)b*DIM + 2*kp)*DIM + 4*d4;
    float4 s0 = *(const float4*)(base);
    float4 s1 = *(const float4*)(base + DIM);
    #pragma unroll
    for (int p=1;p<SPLITS;p++){
        float4 t0 = *(const float4*)(base + p*pstride);
        float4 t1 = *(const float4*)(base + p*pstride + DIM);
        s0.x+=t0.x; s0.y+=t0.y; s0.z+=t0.z; s0.w+=t0.w;
        s1.x+=t1.x; s1.y+=t1.y; s1.z+=t1.z; s1.w+=t1.w;
    }
    uint4 u;
    u.x = pkh(s0.x, s1.x);
    u.y = pkh(s0.y, s1.y);
    u.z = pkh(s0.z, s1.z);
    u.w = pkh(s0.w, s1.w);
    ((uint4*)g_Mh)[((size_t)b*256 + kp)*128 + d4] = u;

    if (gid < BATCH*DIM/4){
        const float4* Vin = (const float4*)g_V;
        float4 s = Vin[gid];
        #pragma unroll
        for (int p=1;p<SPLITS;p++){
            float4 t = Vin[gid + p*(BATCH*DIM/4)];
            s.x+=t.x; s.y+=t.y; s.z+=t.z; s.w+=t.w;
        }
        ((float4*)g_v)[gid] = s;
    }
}

// ---------------------------------------------------------------------------
// Kernel 2: C[b,s,d] = sum_d' W[s,d'] * M[b,d',d] + bias[s]*v[b,d]
// A = W packed by producer (f32->f16x2 pairs along d'); B = g_Mh (pre-packed).
// ---------------------------------------------------------------------------
__global__ void __launch_bounds__(256,3)
k2_proj(const float* __restrict__ Wm, const float* __restrict__ bias, float* __restrict__ out)
{
    __shared__ unsigned Ah[2][TM2][AR2];
    __shared__ unsigned Bh[2][8][PAD1];

    const int tid  = threadIdx.x;
    const int lane = tid & 31;
    const int warp = tid >> 5;
    const int wm = warp & 1, wn = warp >> 1;   // warp tile 32m x 32n
    const int tg = lane & 3;
    const int gp = lane >> 2;

    const int x  = blockIdx.x;
    const int nt = x & 3;
    const int mt = (x >> 2) & 7;
    const int b  = x >> 5;

    // producer coords
    const int am  = tid >> 2;          // 0..63
    const int ak4 = tid & 3;           // float4 within k-chunk
    const int bk  = tid >> 5;          // 0..7 (k-pair row)
    const int bn4 = tid & 31;

    const float* Wp = Wm + (size_t)(mt*TM2 + am)*DIM + 4*ak4;
    const unsigned* Mp = g_Mh + ((size_t)b*256 + bk)*512 + nt*TN + 4*bn4;

    float acc[2][4][4];
    #pragma unroll
    for (int i=0;i<2;i++)
        #pragma unroll
        for (int j=0;j<4;j++)
            #pragma unroll
            for (int r=0;r<4;r++) acc[i][j][r]=0.f;

    float4 wq0, wq1; uint4 mq0, mq1;

    auto ldq = [&](int it, float4& wq, uint4& mq){
        wq = *(const float4*)(Wp + it*TK2);
        mq = *(const uint4*)(Mp + (size_t)it*8*512);
    };
    auto stq = [&](int buf, const float4& wq, const uint4& mq){
        Ah[buf][am][2*ak4]   = pkh(wq.x, wq.y);
        Ah[buf][am][2*ak4+1] = pkh(wq.z, wq.w);
        *(uint4*)&Bh[buf][bk][4*bn4] = mq;
    };
    auto do_mma = [&](int buf){
        unsigned a[2][4];
        #pragma unroll
        for (int i=0;i<2;i++){
            const int mb = 32*wm + 16*i + gp;
            a[i][0] = Ah[buf][mb][tg];
            a[i][1] = Ah[buf][mb+8][tg];
            a[i][2] = Ah[buf][mb][tg+4];
            a[i][3] = Ah[buf][mb+8][tg+4];
        }
        const unsigned* Br0 = Bh[buf][tg];
        const unsigned* Br4 = Bh[buf][tg+4];
        #pragma unroll
        for (int j=0;j<4;j++){
            const int nb = 32*wn + 8*j + gp;
            unsigned b0 = Br0[nb];
            unsigned b1 = Br4[nb];
            mma_f16(acc[0][j], a[0], b0, b1);
            mma_f16(acc[1][j], a[1], b0, b1);
        }
    };

    ldq(0, wq0, mq0);
    stq(0, wq0, mq0);
    ldq(1, wq1, mq1);
    __syncthreads();

    #pragma unroll 1
    for (int it = 0; it < NIT2; it += 2){
        if (it + 2 < NIT2) ldq(it + 2, wq0, mq0);
        if (it + 1 < NIT2) stq(1, wq1, mq1);
        do_mma(0);
        __syncthreads();
        if (it + 3 < NIT2) ldq(it + 3, wq1, mq1);
        if (it + 2 < NIT2) stq(0, wq0, mq0);
        do_mma(1);
        __syncthreads();
    }

    // epilogue: + bias[s]*v[d]
    float* Co = out + (((size_t)b)*DIM + mt*TM2)*DIM + nt*TN;
    float bi[2][2];
    #pragma unroll
    for (int i=0;i<2;i++){
        const int r = 32*wm + 16*i + gp;
        bi[i][0] = bias[mt*TM2 + r];
        bi[i][1] = bias[mt*TM2 + r + 8];
    }
    #pragma unroll
    for (int j=0;j<4;j++){
        const int cc = 32*wn + 8*j + 2*tg;
        const float* vp = g_v + (size_t)b*DIM + nt*TN + cc;
        float v0 = vp[0], v1 = vp[1];
        #pragma unroll
        for (int i=0;i<2;i++){
            const int r = 32*wm + 16*i + gp;
            *(float2*)&Co[(size_t)r*DIM + cc] =
                make_float2(acc[i][j][0] + bi[i][0]*v0, acc[i][j][1] + bi[i][0]*v1);
            *(float2*)&Co[(size_t)(r+8)*DIM + cc] =
                make_float2(acc[i][j][2] + bi[i][1]*v0, acc[i][j][3] + bi[i][1]*v1);
        }
    }
}

extern "C" void kernel_launch(void* const* d_in, const int* in_sizes, int n_in,
                              void* d_out, int out_size)
{
    const float* H    = (const float*)d_in[0];   // hidden_states (4,8192,512)
    const float* E    = (const float*)d_in[1];   // positional_encodings (4,8192,512)
    const float* Wm   = (const float*)d_in[2];   // W (512,512)
    const float* bias = (const float*)d_in[3];   // b (512,)
    float* out = (float*)d_out;                  // (4,512,512)

    k1_outer<<<BATCH*4*4*SPLITS, 256>>>(H, E);
    kred<<<512, 256>>>();
    k2_proj<<<BATCH*8*4, 256>>>(Wm, bias, out);
}